// round 1
// baseline (speedup 1.0000x reference)
#include <cuda_runtime.h>
#include <cstdint>

// ---------------- Problem constants ----------------
constexpr int NUM_USERS = 200000;
constexpr int NUM_ITEMS = 100000;
constexpr int NNODES    = NUM_USERS + NUM_ITEMS;   // 300000
constexpr int D         = 64;
constexpr int K_STEPS   = 4;
constexpr float ALPHA   = 0.1f;
constexpr float BETA    = 0.9f;
// GAMMA = beta^4 + alpha*(1+.9+.81+.729) = 0.6561 + 0.3439 = 1.0 exactly
constexpr float INV_GAMMA = 1.0f;

constexpr int E_MAX     = 1100000;   // headroom over 1,000,000
constexpr int SCAN_BLK  = 1024;
constexpr int NBLK1     = (NNODES + SCAN_BLK - 1) / SCAN_BLK;  // 293

// ---------------- Device scratch (static, allocation-free) ----------------
__device__ int   g_cnt  [NNODES];
__device__ int   g_incl [NNODES];      // per-block inclusive scan
__device__ int   g_bsum [512];         // block sums (NBLK1 <= 512)
__device__ int   g_bexc [512];         // exclusive scan of block sums
__device__ int   g_start[NNODES];
__device__ int   g_pos  [NNODES];
__device__ float g_norm [NNODES];
__device__ int   g_adj  [2 * E_MAX];
__device__ float g_bufA [(size_t)NNODES * D];
__device__ float g_bufB [(size_t)NNODES * D];

// ---------------- Kernels ----------------
__global__ void zero_cnt_kernel() {
    int i = blockIdx.x * blockDim.x + threadIdx.x;
    if (i < NNODES) g_cnt[i] = 0;
}

__global__ void count_kernel(const int* __restrict__ user_idx,
                             const int* __restrict__ item_idx, int E) {
    int e = blockIdx.x * blockDim.x + threadIdx.x;
    if (e >= E) return;
    int u  = user_idx[e];
    int it = NUM_USERS + item_idx[e];
    atomicAdd(&g_cnt[u], 1);
    atomicAdd(&g_cnt[it], 1);
}

// per-block inclusive scan (Hillis-Steele), block sums out
__global__ void scan1_kernel() {
    __shared__ int sh[SCAN_BLK];
    int tid = threadIdx.x;
    int i = blockIdx.x * SCAN_BLK + tid;
    int v = (i < NNODES) ? g_cnt[i] : 0;
    sh[tid] = v;
    __syncthreads();
    for (int off = 1; off < SCAN_BLK; off <<= 1) {
        int t = (tid >= off) ? sh[tid - off] : 0;
        __syncthreads();
        sh[tid] += t;
        __syncthreads();
    }
    if (i < NNODES) g_incl[i] = sh[tid];
    if (tid == SCAN_BLK - 1) g_bsum[blockIdx.x] = sh[tid];
}

// single-block exclusive scan of block sums
__global__ void scan2_kernel() {
    __shared__ int sh[512];
    int tid = threadIdx.x;
    int v = (tid < NBLK1) ? g_bsum[tid] : 0;
    sh[tid] = v;
    __syncthreads();
    for (int off = 1; off < 512; off <<= 1) {
        int t = (tid >= off) ? sh[tid - off] : 0;
        __syncthreads();
        sh[tid] += t;
        __syncthreads();
    }
    g_bexc[tid] = sh[tid] - v;   // exclusive
}

// start offsets, fill cursors, norms
__global__ void finalize_kernel() {
    int i = blockIdx.x * blockDim.x + threadIdx.x;
    if (i >= NNODES) return;
    int c = g_cnt[i];
    int incl = g_incl[i] + g_bexc[i >> 10];
    int st = incl - c;
    g_start[i] = st;
    g_pos[i]   = st;
    g_norm[i]  = rsqrtf((float)(c + 1));   // +1 self loop
}

__global__ void fill_kernel(const int* __restrict__ user_idx,
                            const int* __restrict__ item_idx, int E) {
    int e = blockIdx.x * blockDim.x + threadIdx.x;
    if (e >= E) return;
    int u  = user_idx[e];
    int it = NUM_USERS + item_idx[e];
    int p = atomicAdd(&g_pos[u], 1);
    g_adj[p] = it;
    int q = atomicAdd(&g_pos[it], 1);
    g_adj[q] = u;
}

// s0 = norm[n] * x[n]   (float2-wide, 32 float2 per row)
__global__ void scale_kernel(const float* __restrict__ x, float* __restrict__ s0) {
    int i = blockIdx.x * blockDim.x + threadIdx.x;     // float2 index
    int total = NNODES * (D / 2);
    if (i >= total) return;
    int node = i >> 5;
    float nn = g_norm[node];
    const float2* x2 = (const float2*)x;
    float2 v = x2[i];
    ((float2*)s0)[i] = make_float2(nn * v.x, nn * v.y);
}

// One warp per node. acc = s[n] + sum_{src in adj(n)} s[src].
// h_next = BETA*norm[n]*acc + ALPHA*x[n].
// Non-last: write norm[n]*h_next (keep pre-scaled). Last: write h_next*INV_GAMMA.
template <bool LAST>
__global__ __launch_bounds__(256)
void diffuse_kernel(const float* __restrict__ s_in,
                    const float* __restrict__ x,
                    float* __restrict__ out) {
    int gwarp = (blockIdx.x * blockDim.x + threadIdx.x) >> 5;
    if (gwarp >= NNODES) return;
    int lane = threadIdx.x & 31;

    const float2* s2 = (const float2*)s_in;
    long base = (long)gwarp * (D / 2);   // 32 float2 per row

    float2 acc = s2[base + lane];        // self loop term
    int st = g_start[gwarp];
    int c  = g_cnt[gwarp];
    #pragma unroll 4
    for (int j = 0; j < c; j++) {
        int src = __ldg(&g_adj[st + j]);
        float2 v = s2[(long)src * (D / 2) + lane];
        acc.x += v.x;
        acc.y += v.y;
    }

    float nn = g_norm[gwarp];
    const float2* x2 = (const float2*)x;
    float2 x0 = x2[base + lane];

    float hx = BETA * nn * acc.x + ALPHA * x0.x;
    float hy = BETA * nn * acc.y + ALPHA * x0.y;

    float2 o;
    if (LAST) {
        o = make_float2(hx * INV_GAMMA, hy * INV_GAMMA);
    } else {
        o = make_float2(nn * hx, nn * hy);
    }
    ((float2*)out)[base + lane] = o;
}

// ---------------- Launch ----------------
extern "C" void kernel_launch(void* const* d_in, const int* in_sizes, int n_in,
                              void* d_out, int out_size) {
    const float* x        = (const float*)d_in[0];
    const int*   user_idx = (const int*)d_in[1];
    const int*   item_idx = (const int*)d_in[2];
    float*       out      = (float*)d_out;
    int E = in_sizes[1];

    float *pA, *pB;
    cudaGetSymbolAddress((void**)&pA, g_bufA);
    cudaGetSymbolAddress((void**)&pB, g_bufB);

    // 1. zero degree counts
    zero_cnt_kernel<<<(NNODES + 511) / 512, 512>>>();
    // 2. count degrees
    count_kernel<<<(E + 255) / 256, 256>>>(user_idx, item_idx, E);
    // 3-5. prefix sum -> CSR offsets, norms
    scan1_kernel<<<NBLK1, SCAN_BLK>>>();
    scan2_kernel<<<1, 512>>>();
    finalize_kernel<<<(NNODES + 255) / 256, 256>>>();
    // 6. fill adjacency
    fill_kernel<<<(E + 255) / 256, 256>>>(user_idx, item_idx, E);
    // 7. pre-scale h0
    {
        int total = NNODES * (D / 2);
        scale_kernel<<<(total + 255) / 256, 256>>>(x, pA);
    }
    // 8-11. K=4 diffusion steps (warp per node), ping-pong A->B->A->B, last -> d_out
    int grid = (NNODES * 32 + 255) / 256;   // one warp per node, 8 warps/block
    diffuse_kernel<false><<<grid, 256>>>(pA, x, pB);
    diffuse_kernel<false><<<grid, 256>>>(pB, x, pA);
    diffuse_kernel<false><<<grid, 256>>>(pA, x, pB);
    diffuse_kernel<true ><<<grid, 256>>>(pB, x, out);
}

// round 2
// speedup vs baseline: 1.0674x; 1.0674x over previous
#include <cuda_runtime.h>
#include <cuda_fp16.h>
#include <cstdint>

// ---------------- Problem constants ----------------
constexpr int NUM_USERS = 200000;
constexpr int NUM_ITEMS = 100000;
constexpr int NNODES    = NUM_USERS + NUM_ITEMS;   // 300000
constexpr int D         = 64;
constexpr float ALPHA   = 0.1f;
constexpr float BETA    = 0.9f;
// GAMMA = beta^4 + alpha*(1+.9+.81+.729) = 1.0 exactly
constexpr float INV_GAMMA = 1.0f;

constexpr int E_MAX     = 1100000;
constexpr int SCAN_BLK  = 1024;
constexpr int NBLK1     = (NNODES + SCAN_BLK - 1) / SCAN_BLK;  // 293

// ---------------- Device scratch (static, allocation-free) ----------------
__device__ int    g_cnt  [NNODES];
__device__ int    g_incl [NNODES];
__device__ int    g_bsum [512];
__device__ int    g_bexc [512];
__device__ int    g_start[NNODES];
__device__ int    g_pos  [NNODES];
__device__ float  g_norm [NNODES];
__device__ int    g_adj  [2 * E_MAX];
__device__ __half g_hA   [(size_t)NNODES * D];   // fp16 pre-scaled state (ping)
__device__ __half g_hB   [(size_t)NNODES * D];   // fp16 pre-scaled state (pong)

// ---------------- Preprocessing kernels (unchanged logic) ----------------
__global__ void zero_cnt_kernel() {
    int i = blockIdx.x * blockDim.x + threadIdx.x;
    if (i < NNODES) g_cnt[i] = 0;
}

__global__ void count_kernel(const int* __restrict__ user_idx,
                             const int* __restrict__ item_idx, int E) {
    int e = blockIdx.x * blockDim.x + threadIdx.x;
    if (e >= E) return;
    int u  = user_idx[e];
    int it = NUM_USERS + item_idx[e];
    atomicAdd(&g_cnt[u], 1);
    atomicAdd(&g_cnt[it], 1);
}

__global__ void scan1_kernel() {
    __shared__ int sh[SCAN_BLK];
    int tid = threadIdx.x;
    int i = blockIdx.x * SCAN_BLK + tid;
    int v = (i < NNODES) ? g_cnt[i] : 0;
    sh[tid] = v;
    __syncthreads();
    for (int off = 1; off < SCAN_BLK; off <<= 1) {
        int t = (tid >= off) ? sh[tid - off] : 0;
        __syncthreads();
        sh[tid] += t;
        __syncthreads();
    }
    if (i < NNODES) g_incl[i] = sh[tid];
    if (tid == SCAN_BLK - 1) g_bsum[blockIdx.x] = sh[tid];
}

__global__ void scan2_kernel() {
    __shared__ int sh[512];
    int tid = threadIdx.x;
    int v = (tid < NBLK1) ? g_bsum[tid] : 0;
    sh[tid] = v;
    __syncthreads();
    for (int off = 1; off < 512; off <<= 1) {
        int t = (tid >= off) ? sh[tid - off] : 0;
        __syncthreads();
        sh[tid] += t;
        __syncthreads();
    }
    g_bexc[tid] = sh[tid] - v;
}

__global__ void finalize_kernel() {
    int i = blockIdx.x * blockDim.x + threadIdx.x;
    if (i >= NNODES) return;
    int c = g_cnt[i];
    int incl = g_incl[i] + g_bexc[i >> 10];
    int st = incl - c;
    g_start[i] = st;
    g_pos[i]   = st;
    g_norm[i]  = rsqrtf((float)(c + 1));   // +1 self loop
}

__global__ void fill_kernel(const int* __restrict__ user_idx,
                            const int* __restrict__ item_idx, int E) {
    int e = blockIdx.x * blockDim.x + threadIdx.x;
    if (e >= E) return;
    int u  = user_idx[e];
    int it = NUM_USERS + item_idx[e];
    int p = atomicAdd(&g_pos[u], 1);
    g_adj[p] = it;
    int q = atomicAdd(&g_pos[it], 1);
    g_adj[q] = u;
}

// s0 = fp16(norm[n] * x[n]) : one half2 per thread (32 half2 per row)
__global__ void scale_kernel(const float* __restrict__ x, __half2* __restrict__ s0) {
    int i = blockIdx.x * blockDim.x + threadIdx.x;     // half2 index
    int total = NNODES * (D / 2);
    if (i >= total) return;
    int node = i >> 5;
    float nn = g_norm[node];
    const float2* x2 = (const float2*)x;
    float2 v = x2[i];
    s0[i] = __floats2half2_rn(nn * v.x, nn * v.y);
}

// One warp per node. Each lane owns one half2 (2 feature values).
// acc = s[n] + sum_{src in adj(n)} s[src]  (fp32 accumulation)
// h_next = BETA*norm[n]*acc + ALPHA*x[n]
// Non-last: write fp16(norm[n]*h_next). Last: write fp32 h_next to d_out.
template <bool LAST>
__global__ __launch_bounds__(256)
void diffuse_kernel(const __half2* __restrict__ s_in,
                    const float*   __restrict__ x,
                    __half2*       __restrict__ s_out,
                    float*         __restrict__ out) {
    int gwarp = (blockIdx.x * blockDim.x + threadIdx.x) >> 5;
    if (gwarp >= NNODES) return;
    int lane = threadIdx.x & 31;

    long base = (long)gwarp * (D / 2);   // 32 half2 per row

    float2 acc = __half22float2(s_in[base + lane]);   // self-loop term
    int st = g_start[gwarp];
    int c  = g_cnt[gwarp];

    #pragma unroll 4
    for (int j = 0; j < c; j++) {
        int src = __ldg(&g_adj[st + j]);             // warp-broadcast load
        float2 v = __half22float2(s_in[(long)src * (D / 2) + lane]);
        acc.x += v.x;
        acc.y += v.y;
    }

    float nn = g_norm[gwarp];
    const float2* x2 = (const float2*)x;
    float2 x0 = x2[base + lane];

    float hx = BETA * nn * acc.x + ALPHA * x0.x;
    float hy = BETA * nn * acc.y + ALPHA * x0.y;

    if (LAST) {
        float2 o = make_float2(hx * INV_GAMMA, hy * INV_GAMMA);
        __stcs(((float2*)out) + base + lane, o);     // never re-read: stream out
    } else {
        s_out[base + lane] = __floats2half2_rn(nn * hx, nn * hy);
    }
}

// ---------------- Launch ----------------
extern "C" void kernel_launch(void* const* d_in, const int* in_sizes, int n_in,
                              void* d_out, int out_size) {
    const float* x        = (const float*)d_in[0];
    const int*   user_idx = (const int*)d_in[1];
    const int*   item_idx = (const int*)d_in[2];
    float*       out      = (float*)d_out;
    int E = in_sizes[1];

    __half2 *pA, *pB;
    cudaGetSymbolAddress((void**)&pA, g_hA);
    cudaGetSymbolAddress((void**)&pB, g_hB);

    // CSR build
    zero_cnt_kernel<<<(NNODES + 511) / 512, 512>>>();
    count_kernel<<<(E + 255) / 256, 256>>>(user_idx, item_idx, E);
    scan1_kernel<<<NBLK1, SCAN_BLK>>>();
    scan2_kernel<<<1, 512>>>();
    finalize_kernel<<<(NNODES + 255) / 256, 256>>>();
    fill_kernel<<<(E + 255) / 256, 256>>>(user_idx, item_idx, E);

    // s0 = fp16(norm * x)
    {
        int total = NNODES * (D / 2);
        scale_kernel<<<(total + 255) / 256, 256>>>(x, pA);
    }

    // K=4 diffusion steps, warp per node, ping-pong fp16 state
    int grid = (NNODES * 32 + 255) / 256;
    diffuse_kernel<false><<<grid, 256>>>(pA, x, pB, nullptr);
    diffuse_kernel<false><<<grid, 256>>>(pB, x, pA, nullptr);
    diffuse_kernel<false><<<grid, 256>>>(pA, x, pB, nullptr);
    diffuse_kernel<true ><<<grid, 256>>>(pB, x, nullptr, out);
}